// round 10
// baseline (speedup 1.0000x reference)
#include <cuda_runtime.h>
#include <cuda_bf16.h>
#include <math.h>
#include <stdint.h>

#define B_  64
#define N_  900   // queries
#define C_  91    // classes
#define M_  128   // targets

#define INF_D 1e18
#define FULLM 0xFFFFFFFFu

// Scratch (allocation-free rule: __device__ globals)
__device__ float g_costT[(size_t)B_ * M_ * N_];   // [b][m][n]
__device__ float g_smax[(size_t)B_ * N_];
__device__ float g_ssum[(size_t)B_ * N_];
__device__ int   g_rows[B_ * M_];
__device__ int   g_cols[B_ * M_];

// ---------------------------------------------------------------------------
// Kernel 1: per-(b,n) softmax stats over 91 classes. One warp per row.
// ---------------------------------------------------------------------------
__global__ void softmax_stats_kernel(const float* __restrict__ logits) {
    int warp = (blockIdx.x * blockDim.x + threadIdx.x) >> 5;
    int lane = threadIdx.x & 31;
    if (warp >= B_ * N_) return;
    const float* row = logits + (size_t)warp * C_;

    float mx = -INFINITY;
    for (int c = lane; c < C_; c += 32) mx = fmaxf(mx, row[c]);
    #pragma unroll
    for (int o = 16; o; o >>= 1) mx = fmaxf(mx, __shfl_xor_sync(FULLM, mx, o));

    float s = 0.f;
    for (int c = lane; c < C_; c += 32) s += expf(row[c] - mx);
    #pragma unroll
    for (int o = 16; o; o >>= 1) s += __shfl_xor_sync(FULLM, s, o);

    if (lane == 0) { g_smax[warp] = mx; g_ssum[warp] = s; }
}

// ---------------------------------------------------------------------------
// Kernel 2: cost matrix, transposed layout costT[b][m][n].
// ---------------------------------------------------------------------------
__global__ void cost_kernel(const float* __restrict__ logits,
                            const float* __restrict__ pboxes,
                            const int* __restrict__ tlabels,
                            const float* __restrict__ tboxes) {
    int m = blockIdx.x;
    int b = blockIdx.y;
    int idx = b * M_ + m;

    int cls = tlabels[idx];

    const float* tbp = tboxes + (size_t)idx * 4;
    float tcx = tbp[0], tcy = tbp[1], tw = tbp[2], th = tbp[3];
    float tx0 = tcx - 0.5f * tw, ty0 = tcy - 0.5f * th;
    float tx1 = tcx + 0.5f * tw, ty1 = tcy + 0.5f * th;
    float tarea = (tx1 - tx0) * (ty1 - ty0);

    float* out = g_costT + (size_t)idx * N_;

    for (int n = threadIdx.x; n < N_; n += blockDim.x) {
        size_t rn = (size_t)b * N_ + n;
        const float* pp = pboxes + rn * 4;
        float pcx = pp[0], pcy = pp[1], pw = pp[2], ph = pp[3];

        float l = logits[rn * C_ + cls];
        float prob = expf(l - g_smax[rn]) / g_ssum[rn];

        float l1 = fabsf(pcx - tcx) + fabsf(pcy - tcy)
                 + fabsf(pw - tw) + fabsf(ph - th);

        float px0 = pcx - 0.5f * pw, py0 = pcy - 0.5f * ph;
        float px1 = pcx + 0.5f * pw, py1 = pcy + 0.5f * ph;

        float iw = fmaxf(fminf(px1, tx1) - fmaxf(px0, tx0), 0.f);
        float ih = fmaxf(fminf(py1, ty1) - fmaxf(py0, ty0), 0.f);
        float inter = iw * ih;
        float area1 = (px1 - px0) * (py1 - py0);
        float uni = area1 + tarea - inter;
        float iou = inter / (uni + 1e-6f);
        float enc = (fmaxf(px1, tx1) - fminf(px0, tx0)) *
                    (fmaxf(py1, ty1) - fminf(py0, ty0)) + 1e-6f;
        float giou = iou - (enc - uni) / enc;

        out[n] = -prob + 5.f * l1 - 2.f * giou;
    }
}

// ---------------------------------------------------------------------------
// Kernel 3: Jonker-Volgenant LSA, one warp per batch (float64, reference
// op order + first-index argmin tie-break). Certified optimal in R9 via
// LP-duality check (viol_neg = viol_tight = 0 on all batches).
// ---------------------------------------------------------------------------
__global__ void __launch_bounds__(32, 1)
lsa_warp_kernel() {
    int b = blockIdx.x;
    int lane = threadIdx.x;
    const float* cost = g_costT + (size_t)b * M_ * N_;

    __shared__ double u[M_ + 1];
    __shared__ double v[N_ + 1];
    __shared__ double minv[N_ + 1];
    __shared__ int    way[N_ + 1];
    __shared__ int    p[N_ + 1];
    __shared__ int    used[N_ + 1];
    __shared__ int    col4row[M_];

    for (int j = lane; j <= N_; j += 32) { v[j] = 0.0; p[j] = 0; }
    for (int i = lane; i <= M_; i += 32) u[i] = 0.0;
    __syncwarp();

    for (int i = 1; i <= M_; ++i) {
        if (lane == 0) p[0] = i;
        for (int j = lane; j <= N_; j += 32) {
            minv[j] = INF_D; used[j] = 0; way[j] = 0;
        }
        __syncwarp();

        int j0 = 0;
        while (true) {
            if (lane == 0) used[j0] = 1;
            __syncwarp();

            int i0 = p[j0];
            double ui0 = u[i0];
            const float* crow = cost + (size_t)(i0 - 1) * N_;

            double best = INF_D;
            int bestj = N_ + 2;
            for (int j = 1 + lane; j <= N_; j += 32) {
                if (!used[j]) {
                    double cur = (double)crow[j - 1] - ui0 - v[j];
                    if (cur < minv[j]) { minv[j] = cur; way[j] = j0; }
                    double mv = minv[j];
                    if (mv < best || (mv == best && j < bestj)) { best = mv; bestj = j; }
                }
            }
            __syncwarp();
            #pragma unroll
            for (int o = 16; o; o >>= 1) {
                double ov = __shfl_down_sync(FULLM, best, o);
                int    oi = __shfl_down_sync(FULLM, bestj, o);
                if (ov < best || (ov == best && oi < bestj)) { best = ov; bestj = oi; }
            }
            double delta = __shfl_sync(FULLM, best, 0);
            int    j1    = __shfl_sync(FULLM, bestj, 0);

            for (int j = lane; j <= N_; j += 32) {
                if (used[j]) { u[p[j]] += delta; v[j] -= delta; }
                else if (j >= 1) minv[j] -= delta;
            }
            __syncwarp();

            j0 = j1;
            if (p[j0] == 0) break;
        }

        if (lane == 0) {
            int jj = j0;
            while (jj) { int jn = way[jj]; p[jj] = p[jn]; jj = jn; }
        }
        __syncwarp();
    }

    for (int j = 1 + lane; j <= N_; j += 32)
        if (p[j] > 0) col4row[p[j] - 1] = j - 1;
    __syncwarp();

    // transposed output: rows = sorted assigned queries, cols = target order
    for (int t = lane; t < M_; t += 32) {
        int vme = col4row[t];
        int r = 0;
        #pragma unroll 8
        for (int k = 0; k < M_; ++k) r += (col4row[k] < vme);
        g_rows[b * M_ + r] = vme;
        g_cols[b * M_ + r] = t;
    }
}

// ---------------------------------------------------------------------------
// Kernel 4: emit output as FLOAT32 (the harness compares output.bin with
// np.frombuffer(dtype=np.float32) — discovered R9, line T495).
// Layout: rows (B*M) then cols (B*M).
// ---------------------------------------------------------------------------
__global__ void emit_kernel(float* __restrict__ d_out) {
    int i = blockIdx.x * blockDim.x + threadIdx.x;
    if (i >= 2 * B_ * M_) return;
    int val = (i < B_ * M_) ? g_rows[i] : g_cols[i - B_ * M_];
    d_out[i] = (float)val;
}

// ---------------------------------------------------------------------------
extern "C" void kernel_launch(void* const* d_in, const int* in_sizes, int n_in,
                              void* d_out, int out_size) {
    const float* logits  = (const float*)d_in[0];  // (64,900,91) f32
    const float* pboxes  = (const float*)d_in[1];  // (64,900,4)  f32
    const int*   tlabels = (const int*)d_in[2];    // (64,128)    int32 (confirmed R9)
    const float* tboxes  = (const float*)d_in[3];  // (64,128,4)  f32

    softmax_stats_kernel<<<(B_ * N_ * 32 + 255) / 256, 256>>>(logits);
    {
        dim3 grid(M_, B_);
        cost_kernel<<<grid, 256>>>(logits, pboxes, tlabels, tboxes);
    }
    lsa_warp_kernel<<<B_, 32>>>();
    emit_kernel<<<(2 * B_ * M_ + 255) / 256, 256>>>((float*)d_out);
}

// round 11
// speedup vs baseline: 4.3608x; 4.3608x over previous
#include <cuda_runtime.h>
#include <cuda_bf16.h>
#include <math.h>
#include <stdint.h>

#define B_  64
#define N_  900   // queries
#define C_  91    // classes
#define M_  128   // targets

#define INF_D 1e18
#define FULLM 0xFFFFFFFFu
#define TLSA 256

// Scratch (allocation-free rule: __device__ globals)
__device__ float g_costT[(size_t)B_ * M_ * N_];   // [b][m][n]
__device__ float g_smax[(size_t)B_ * N_];
__device__ float g_ssum[(size_t)B_ * N_];
__device__ int   g_rows[B_ * M_];
__device__ int   g_cols[B_ * M_];

// Monotonic double->uint64 map: preserves < order for all non-NaN doubles.
__device__ __forceinline__ unsigned long long dmap(double d) {
    unsigned long long x = __double_as_longlong(d);
    return (x & 0x8000000000000000ull) ? ~x : (x | 0x8000000000000000ull);
}
__device__ __forceinline__ double dunmap(unsigned long long k) {
    return (k & 0x8000000000000000ull)
        ? __longlong_as_double(k & 0x7FFFFFFFFFFFFFFFull)
        : __longlong_as_double(~k);
}

// ---------------------------------------------------------------------------
// Kernel 1: per-(b,n) softmax stats over 91 classes. One warp per row.
// ---------------------------------------------------------------------------
__global__ void softmax_stats_kernel(const float* __restrict__ logits) {
    int warp = (blockIdx.x * blockDim.x + threadIdx.x) >> 5;
    int lane = threadIdx.x & 31;
    if (warp >= B_ * N_) return;
    const float* row = logits + (size_t)warp * C_;

    float mx = -INFINITY;
    for (int c = lane; c < C_; c += 32) mx = fmaxf(mx, row[c]);
    #pragma unroll
    for (int o = 16; o; o >>= 1) mx = fmaxf(mx, __shfl_xor_sync(FULLM, mx, o));

    float s = 0.f;
    for (int c = lane; c < C_; c += 32) s += expf(row[c] - mx);
    #pragma unroll
    for (int o = 16; o; o >>= 1) s += __shfl_xor_sync(FULLM, s, o);

    if (lane == 0) { g_smax[warp] = mx; g_ssum[warp] = s; }
}

// ---------------------------------------------------------------------------
// Kernel 2: cost matrix, transposed layout costT[b][m][n].
// ---------------------------------------------------------------------------
__global__ void cost_kernel(const float* __restrict__ logits,
                            const float* __restrict__ pboxes,
                            const int* __restrict__ tlabels,
                            const float* __restrict__ tboxes) {
    int m = blockIdx.x;
    int b = blockIdx.y;
    int idx = b * M_ + m;

    int cls = tlabels[idx];

    const float* tbp = tboxes + (size_t)idx * 4;
    float tcx = tbp[0], tcy = tbp[1], tw = tbp[2], th = tbp[3];
    float tx0 = tcx - 0.5f * tw, ty0 = tcy - 0.5f * th;
    float tx1 = tcx + 0.5f * tw, ty1 = tcy + 0.5f * th;
    float tarea = (tx1 - tx0) * (ty1 - ty0);

    float* out = g_costT + (size_t)idx * N_;

    for (int n = threadIdx.x; n < N_; n += blockDim.x) {
        size_t rn = (size_t)b * N_ + n;
        const float* pp = pboxes + rn * 4;
        float pcx = pp[0], pcy = pp[1], pw = pp[2], ph = pp[3];

        float l = logits[rn * C_ + cls];
        float prob = expf(l - g_smax[rn]) / g_ssum[rn];

        float l1 = fabsf(pcx - tcx) + fabsf(pcy - tcy)
                 + fabsf(pw - tw) + fabsf(ph - th);

        float px0 = pcx - 0.5f * pw, py0 = pcy - 0.5f * ph;
        float px1 = pcx + 0.5f * pw, py1 = pcy + 0.5f * ph;

        float iw = fmaxf(fminf(px1, tx1) - fmaxf(px0, tx0), 0.f);
        float ih = fmaxf(fminf(py1, ty1) - fmaxf(py0, ty0), 0.f);
        float inter = iw * ih;
        float area1 = (px1 - px0) * (py1 - py0);
        float uni = area1 + tarea - inter;
        float iou = inter / (uni + 1e-6f);
        float enc = (fmaxf(px1, tx1) - fminf(px0, tx0)) *
                    (fmaxf(py1, ty1) - fminf(py0, ty0)) + 1e-6f;
        float giou = iou - (enc - uni) / enc;

        out[n] = -prob + 5.f * l1 - 2.f * giou;
    }
}

// ---------------------------------------------------------------------------
// Kernel 3: JV LSA, 256-thread block per batch, register-resident columns.
// Thread t owns 0-based columns t, t+256, t+512, t+768 (slot 3 only t<132).
// FP64 kept exactly where the reference uses it (same op order -> bit-exact
// assignments); comparisons via monotonic uint64 keys (ALU, not DSETP).
// ---------------------------------------------------------------------------
__global__ void __launch_bounds__(TLSA, 1)
lsa_block_kernel() {
    int b = blockIdx.x;
    int tid = threadIdx.x;
    const float* cost = g_costT + (size_t)b * M_ * N_;

    __shared__ double u[M_ + 1];
    __shared__ int    p[N_ + 1];
    __shared__ int    way[N_ + 1];
    __shared__ unsigned long long red_k[TLSA / 32];
    __shared__ int    red_j[TLSA / 32];
    __shared__ int    j0_sh, done_sh;
    __shared__ double delta_sh;
    __shared__ int    col4row[M_];

    // per-thread columns (0-based): c_s = tid + 256*s
    const int cA = tid, cB = tid + 256, cC = tid + 512, cD = tid + 768;
    const bool ownD = (cD < N_);            // slots A,B,C always valid (<900)

    double vA = 0.0, vB = 0.0, vC = 0.0, vD = 0.0;
    double mA, mB, mC, mD;
    unsigned um;                             // used bitmask, bits 0..3

    for (int i = tid; i <= M_; i += TLSA) u[i] = 0.0;
    for (int j = tid; j <= N_; j += TLSA) p[j] = 0;
    __syncthreads();

    for (int i = 1; i <= M_; ++i) {
        if (tid == 0) { p[0] = i; j0_sh = 0; }
        mA = INF_D; mB = INF_D; mC = INF_D; mD = INF_D;
        um = 0;
        __syncthreads();

        while (true) {
            int j0 = j0_sh;
            // mark used: 1-based column j0 -> 0-based c = j0-1, owner c&255
            if (j0 >= 1) {
                int c = j0 - 1;
                if ((c & 255) == tid) um |= 1u << (c >> 8);
            }
            int i0 = p[j0];
            double ui0 = u[i0];
            const float* crow = cost + (size_t)(i0 - 1) * N_;

            unsigned long long bk = 0xFFFFFFFFFFFFFFFFull;
            int bj = N_ + 2;
            // slot A
            if (!(um & 1u)) {
                double cur = (double)crow[cA] - ui0 - vA;
                if (cur < mA) { mA = cur; way[cA + 1] = j0; }
                unsigned long long k = dmap(mA);
                if (k < bk) { bk = k; bj = cA + 1; }
            }
            // slot B
            if (!(um & 2u)) {
                double cur = (double)crow[cB] - ui0 - vB;
                if (cur < mB) { mB = cur; way[cB + 1] = j0; }
                unsigned long long k = dmap(mB);
                if (k < bk || (k == bk && cB + 1 < bj)) { bk = k; bj = cB + 1; }
            }
            // slot C
            if (!(um & 4u)) {
                double cur = (double)crow[cC] - ui0 - vC;
                if (cur < mC) { mC = cur; way[cC + 1] = j0; }
                unsigned long long k = dmap(mC);
                if (k < bk || (k == bk && cC + 1 < bj)) { bk = k; bj = cC + 1; }
            }
            // slot D
            if (ownD && !(um & 8u)) {
                double cur = (double)crow[cD] - ui0 - vD;
                if (cur < mD) { mD = cur; way[cD + 1] = j0; }
                unsigned long long k = dmap(mD);
                if (k < bk || (k == bk && cD + 1 < bj)) { bk = k; bj = cD + 1; }
            }

            // warp reduce (min key, then min index)
            #pragma unroll
            for (int o = 16; o; o >>= 1) {
                unsigned long long ok = __shfl_down_sync(FULLM, bk, o);
                int oj = __shfl_down_sync(FULLM, bj, o);
                if (ok < bk || (ok == bk && oj < bj)) { bk = ok; bj = oj; }
            }
            if ((tid & 31) == 0) { red_k[tid >> 5] = bk; red_j[tid >> 5] = bj; }
            __syncthreads();

            if (tid == 0) {
                unsigned long long fk = red_k[0]; int fj = red_j[0];
                #pragma unroll
                for (int w = 1; w < TLSA / 32; ++w) {
                    if (red_k[w] < fk || (red_k[w] == fk && red_j[w] < fj)) {
                        fk = red_k[w]; fj = red_j[w];
                    }
                }
                double delta = dunmap(fk);
                delta_sh = delta;
                u[p[0]] += delta;            // virtual column 0 is always used
                j0_sh = fj;
                done_sh = (p[fj] == 0);
            }
            __syncthreads();

            double delta = delta_sh;
            // numpy: u[p[used]] += delta; v[used] -= delta; minv[free] -= delta
            if (um & 1u) { vA -= delta; u[p[cA + 1]] += delta; } else mA -= delta;
            if (um & 2u) { vB -= delta; u[p[cB + 1]] += delta; } else mB -= delta;
            if (um & 4u) { vC -= delta; u[p[cC + 1]] += delta; } else mC -= delta;
            if (ownD) {
                if (um & 8u) { vD -= delta; u[p[cD + 1]] += delta; } else mD -= delta;
            }
            __syncthreads();

            if (done_sh) break;
        }

        // augment along alternating path (serial, short)
        if (tid == 0) {
            int jj = j0_sh;
            while (jj) { int jn = way[jj]; p[jj] = p[jn]; jj = jn; }
        }
        __syncthreads();
    }

    // col4row[target] = assigned query
    for (int j = 1 + tid; j <= N_; j += TLSA)
        if (p[j] > 0) col4row[p[j] - 1] = j - 1;
    __syncthreads();

    // transposed output: rows = sorted assigned queries, cols = target order
    if (tid < M_) {
        int vme = col4row[tid];
        int r = 0;
        #pragma unroll 8
        for (int k = 0; k < M_; ++k) r += (col4row[k] < vme);
        g_rows[b * M_ + r] = vme;
        g_cols[b * M_ + r] = tid;
    }
}

// ---------------------------------------------------------------------------
// Kernel 4: emit output as FLOAT32 (harness compares output.bin as float32).
// Layout: rows (B*M) then cols (B*M).
// ---------------------------------------------------------------------------
__global__ void emit_kernel(float* __restrict__ d_out) {
    int i = blockIdx.x * blockDim.x + threadIdx.x;
    if (i >= 2 * B_ * M_) return;
    int val = (i < B_ * M_) ? g_rows[i] : g_cols[i - B_ * M_];
    d_out[i] = (float)val;
}

// ---------------------------------------------------------------------------
extern "C" void kernel_launch(void* const* d_in, const int* in_sizes, int n_in,
                              void* d_out, int out_size) {
    const float* logits  = (const float*)d_in[0];  // (64,900,91) f32
    const float* pboxes  = (const float*)d_in[1];  // (64,900,4)  f32
    const int*   tlabels = (const int*)d_in[2];    // (64,128)    int32
    const float* tboxes  = (const float*)d_in[3];  // (64,128,4)  f32

    softmax_stats_kernel<<<(B_ * N_ * 32 + 255) / 256, 256>>>(logits);
    {
        dim3 grid(M_, B_);
        cost_kernel<<<grid, 256>>>(logits, pboxes, tlabels, tboxes);
    }
    lsa_block_kernel<<<B_, TLSA>>>();
    emit_kernel<<<(2 * B_ * M_ + 255) / 256, 256>>>((float*)d_out);
}

// round 12
// speedup vs baseline: 5.0344x; 1.1545x over previous
#include <cuda_runtime.h>
#include <cuda_bf16.h>
#include <math.h>
#include <stdint.h>

#define B_  64
#define N_  900   // queries
#define C_  91    // classes
#define M_  128   // targets

#define INF_D 1e18
#define FULLM 0xFFFFFFFFu
#define TLSA 256

// Scratch (allocation-free rule: __device__ globals)
__device__ float g_costT[(size_t)B_ * M_ * N_];   // [b][m][n]
__device__ float g_smax[(size_t)B_ * N_];
__device__ float g_ssum[(size_t)B_ * N_];
__device__ int   g_rows[B_ * M_];
__device__ int   g_cols[B_ * M_];

// Monotonic double->uint64 map: preserves < order for all non-NaN doubles.
__device__ __forceinline__ unsigned long long dmap(double d) {
    unsigned long long x = __double_as_longlong(d);
    return (x & 0x8000000000000000ull) ? ~x : (x | 0x8000000000000000ull);
}
__device__ __forceinline__ double dunmap(unsigned long long k) {
    return (k & 0x8000000000000000ull)
        ? __longlong_as_double(k & 0x7FFFFFFFFFFFFFFFull)
        : __longlong_as_double(~k);
}

// ---------------------------------------------------------------------------
// Kernel 1: per-(b,n) softmax stats over 91 classes. One warp per row.
// ---------------------------------------------------------------------------
__global__ void softmax_stats_kernel(const float* __restrict__ logits) {
    int warp = (blockIdx.x * blockDim.x + threadIdx.x) >> 5;
    int lane = threadIdx.x & 31;
    if (warp >= B_ * N_) return;
    const float* row = logits + (size_t)warp * C_;

    float mx = -INFINITY;
    for (int c = lane; c < C_; c += 32) mx = fmaxf(mx, row[c]);
    #pragma unroll
    for (int o = 16; o; o >>= 1) mx = fmaxf(mx, __shfl_xor_sync(FULLM, mx, o));

    float s = 0.f;
    for (int c = lane; c < C_; c += 32) s += expf(row[c] - mx);
    #pragma unroll
    for (int o = 16; o; o >>= 1) s += __shfl_xor_sync(FULLM, s, o);

    if (lane == 0) { g_smax[warp] = mx; g_ssum[warp] = s; }
}

// ---------------------------------------------------------------------------
// Kernel 2: cost matrix, transposed layout costT[b][m][n].
// ---------------------------------------------------------------------------
__global__ void cost_kernel(const float* __restrict__ logits,
                            const float* __restrict__ pboxes,
                            const int* __restrict__ tlabels,
                            const float* __restrict__ tboxes) {
    int m = blockIdx.x;
    int b = blockIdx.y;
    int idx = b * M_ + m;

    int cls = tlabels[idx];

    const float* tbp = tboxes + (size_t)idx * 4;
    float tcx = tbp[0], tcy = tbp[1], tw = tbp[2], th = tbp[3];
    float tx0 = tcx - 0.5f * tw, ty0 = tcy - 0.5f * th;
    float tx1 = tcx + 0.5f * tw, ty1 = tcy + 0.5f * th;
    float tarea = (tx1 - tx0) * (ty1 - ty0);

    float* out = g_costT + (size_t)idx * N_;

    for (int n = threadIdx.x; n < N_; n += blockDim.x) {
        size_t rn = (size_t)b * N_ + n;
        const float* pp = pboxes + rn * 4;
        float pcx = pp[0], pcy = pp[1], pw = pp[2], ph = pp[3];

        float l = logits[rn * C_ + cls];
        float prob = expf(l - g_smax[rn]) / g_ssum[rn];

        float l1 = fabsf(pcx - tcx) + fabsf(pcy - tcy)
                 + fabsf(pw - tw) + fabsf(ph - th);

        float px0 = pcx - 0.5f * pw, py0 = pcy - 0.5f * ph;
        float px1 = pcx + 0.5f * pw, py1 = pcy + 0.5f * ph;

        float iw = fmaxf(fminf(px1, tx1) - fmaxf(px0, tx0), 0.f);
        float ih = fmaxf(fminf(py1, ty1) - fmaxf(py0, ty0), 0.f);
        float inter = iw * ih;
        float area1 = (px1 - px0) * (py1 - py0);
        float uni = area1 + tarea - inter;
        float iou = inter / (uni + 1e-6f);
        float enc = (fmaxf(px1, tx1) - fminf(px0, tx0)) *
                    (fmaxf(py1, ty1) - fminf(py0, ty0)) + 1e-6f;
        float giou = iou - (enc - uni) / enc;

        out[n] = -prob + 5.f * l1 - 2.f * giou;
    }
}

// ---------------------------------------------------------------------------
// Kernel 3: JV LSA, 256-thread block per batch, register-resident columns.
// Two barriers per inner iteration: the delta update (step 4 of numpy's
// loop) is merged into the top of the next iteration; safe because the new
// i0 = p[j1] has its u untouched by that update (j1 was free; p injective).
// Cost-row loads issued before the update math to hide L2 latency.
// ---------------------------------------------------------------------------
__global__ void __launch_bounds__(TLSA, 1)
lsa_block_kernel() {
    int b = blockIdx.x;
    int tid = threadIdx.x;
    const float* cost = g_costT + (size_t)b * M_ * N_;

    __shared__ double u[M_ + 1];
    __shared__ int    p[N_ + 1];
    __shared__ int    way[N_ + 1];
    __shared__ unsigned long long red_k[TLSA / 32];
    __shared__ int    red_j[TLSA / 32];
    __shared__ int    j0_sh, done_sh;
    __shared__ double delta_sh;
    __shared__ int    col4row[M_];

    const int cA = tid, cB = tid + 256, cC = tid + 512, cD = tid + 768;
    const bool ownD = (cD < N_);

    double vA = 0.0, vB = 0.0, vC = 0.0, vD = 0.0;
    double mA, mB, mC, mD;
    unsigned um;

    for (int i = tid; i <= M_; i += TLSA) u[i] = 0.0;
    for (int j = tid; j <= N_; j += TLSA) p[j] = 0;
    __syncthreads();

    for (int i = 1; i <= M_; ++i) {
        if (tid == 0) { p[0] = i; j0_sh = 0; done_sh = 0; }
        mA = INF_D; mB = INF_D; mC = INF_D; mD = INF_D;
        um = 0;
        bool first = true;

        while (true) {
            __syncthreads();                 // barrier A
            int j0 = j0_sh;

            // --- apply previous iteration's delta update (numpy step 4) ---
            if (!first) {
                double delta = delta_sh;
                if (um & 1u) { vA -= delta; u[p[cA + 1]] += delta; } else mA -= delta;
                if (um & 2u) { vB -= delta; u[p[cB + 1]] += delta; } else mB -= delta;
                if (um & 4u) { vC -= delta; u[p[cC + 1]] += delta; } else mC -= delta;
                if (ownD) {
                    if (um & 8u) { vD -= delta; u[p[cD + 1]] += delta; } else mD -= delta;
                }
            }
            if (done_sh) break;
            first = false;

            // mark new j0 used (owner thread)
            if (j0 >= 1) {
                int c = j0 - 1;
                if ((c & 255) == tid) um |= 1u << (c >> 8);
            }

            int i0 = p[j0];
            const float* crow = cost + (size_t)(i0 - 1) * N_;
            // issue loads early — overlap with nothing above, but compiler
            // hoists them ahead of the FP64 scan chain below
            float fA = crow[cA];
            float fB = crow[cB];
            float fC = crow[cC];
            float fD = ownD ? crow[cD] : 0.f;
            double ui0 = u[i0];

            unsigned long long bk = 0xFFFFFFFFFFFFFFFFull;
            int bj = N_ + 2;
            if (!(um & 1u)) {
                double cur = (double)fA - ui0 - vA;
                if (cur < mA) { mA = cur; way[cA + 1] = j0; }
                unsigned long long k = dmap(mA);
                if (k < bk) { bk = k; bj = cA + 1; }
            }
            if (!(um & 2u)) {
                double cur = (double)fB - ui0 - vB;
                if (cur < mB) { mB = cur; way[cB + 1] = j0; }
                unsigned long long k = dmap(mB);
                if (k < bk || (k == bk && cB + 1 < bj)) { bk = k; bj = cB + 1; }
            }
            if (!(um & 4u)) {
                double cur = (double)fC - ui0 - vC;
                if (cur < mC) { mC = cur; way[cC + 1] = j0; }
                unsigned long long k = dmap(mC);
                if (k < bk || (k == bk && cC + 1 < bj)) { bk = k; bj = cC + 1; }
            }
            if (ownD && !(um & 8u)) {
                double cur = (double)fD - ui0 - vD;
                if (cur < mD) { mD = cur; way[cD + 1] = j0; }
                unsigned long long k = dmap(mD);
                if (k < bk || (k == bk && cD + 1 < bj)) { bk = k; bj = cD + 1; }
            }

            // warp reduce (min key, first index)
            #pragma unroll
            for (int o = 16; o; o >>= 1) {
                unsigned long long ok = __shfl_down_sync(FULLM, bk, o);
                int oj = __shfl_down_sync(FULLM, bj, o);
                if (ok < bk || (ok == bk && oj < bj)) { bk = ok; bj = oj; }
            }
            if ((tid & 31) == 0) { red_k[tid >> 5] = bk; red_j[tid >> 5] = bj; }
            __syncthreads();                 // barrier B

            // stage-2 reduce: warp 0 lanes 0..7 in 3 shfl steps
            if (tid < 32) {
                unsigned long long fk = (tid < TLSA / 32) ? red_k[tid]
                                                          : 0xFFFFFFFFFFFFFFFFull;
                int fj = (tid < TLSA / 32) ? red_j[tid] : N_ + 2;
                #pragma unroll
                for (int o = 4; o; o >>= 1) {
                    unsigned long long ok = __shfl_down_sync(FULLM, fk, o);
                    int oj = __shfl_down_sync(FULLM, fj, o);
                    if (ok < fk || (ok == fk && oj < fj)) { fk = ok; fj = oj; }
                }
                if (tid == 0) {
                    double delta = dunmap(fk);
                    delta_sh = delta;
                    u[p[0]] += delta;        // virtual column 0 always used
                    j0_sh = fj;
                    done_sh = (p[fj] == 0);
                }
            }
        }

        // augment (serial, short); other threads proceed to next row's
        // barrier A, which orders these p[] writes before their next reads.
        if (tid == 0) {
            int jj = j0_sh;
            while (jj) { int jn = way[jj]; p[jj] = p[jn]; jj = jn; }
        }
    }
    __syncthreads();

    for (int j = 1 + tid; j <= N_; j += TLSA)
        if (p[j] > 0) col4row[p[j] - 1] = j - 1;
    __syncthreads();

    if (tid < M_) {
        int vme = col4row[tid];
        int r = 0;
        #pragma unroll 8
        for (int k = 0; k < M_; ++k) r += (col4row[k] < vme);
        g_rows[b * M_ + r] = vme;
        g_cols[b * M_ + r] = tid;
    }
}

// ---------------------------------------------------------------------------
// Kernel 4: emit output as FLOAT32 (harness compares output.bin as float32).
// ---------------------------------------------------------------------------
__global__ void emit_kernel(float* __restrict__ d_out) {
    int i = blockIdx.x * blockDim.x + threadIdx.x;
    if (i >= 2 * B_ * M_) return;
    int val = (i < B_ * M_) ? g_rows[i] : g_cols[i - B_ * M_];
    d_out[i] = (float)val;
}

// ---------------------------------------------------------------------------
extern "C" void kernel_launch(void* const* d_in, const int* in_sizes, int n_in,
                              void* d_out, int out_size) {
    const float* logits  = (const float*)d_in[0];
    const float* pboxes  = (const float*)d_in[1];
    const int*   tlabels = (const int*)d_in[2];
    const float* tboxes  = (const float*)d_in[3];

    softmax_stats_kernel<<<(B_ * N_ * 32 + 255) / 256, 256>>>(logits);
    {
        dim3 grid(M_, B_);
        cost_kernel<<<grid, 256>>>(logits, pboxes, tlabels, tboxes);
    }
    lsa_block_kernel<<<B_, TLSA>>>();
    emit_kernel<<<(2 * B_ * M_ + 255) / 256, 256>>>((float*)d_out);
}

// round 13
// speedup vs baseline: 12.4413x; 2.4713x over previous
#include <cuda_runtime.h>
#include <cuda_bf16.h>
#include <math.h>
#include <stdint.h>

#define B_  64
#define N_  900   // queries
#define C_  91    // classes
#define M_  128   // targets

#define INF_D 1e18
#define FULLM 0xFFFFFFFFu
#define TLSA 256

// Scratch (allocation-free rule: __device__ globals)
__device__ float g_costT[(size_t)B_ * M_ * N_];   // [b][m][n]
__device__ float g_smax[(size_t)B_ * N_];
__device__ float g_ssum[(size_t)B_ * N_];
__device__ int   g_rows[B_ * M_];
__device__ int   g_cols[B_ * M_];

// Monotonic double->uint64 map: preserves < order for all non-NaN doubles.
__device__ __forceinline__ unsigned long long dmap(double d) {
    unsigned long long x = __double_as_longlong(d);
    return (x & 0x8000000000000000ull) ? ~x : (x | 0x8000000000000000ull);
}
__device__ __forceinline__ double dunmap(unsigned long long k) {
    return (k & 0x8000000000000000ull)
        ? __longlong_as_double(k & 0x7FFFFFFFFFFFFFFFull)
        : __longlong_as_double(~k);
}

// ---------------------------------------------------------------------------
// Kernel 1: per-(b,n) softmax stats over 91 classes. One warp per row.
// ---------------------------------------------------------------------------
__global__ void softmax_stats_kernel(const float* __restrict__ logits) {
    int warp = (blockIdx.x * blockDim.x + threadIdx.x) >> 5;
    int lane = threadIdx.x & 31;
    if (warp >= B_ * N_) return;
    const float* row = logits + (size_t)warp * C_;

    float mx = -INFINITY;
    for (int c = lane; c < C_; c += 32) mx = fmaxf(mx, row[c]);
    #pragma unroll
    for (int o = 16; o; o >>= 1) mx = fmaxf(mx, __shfl_xor_sync(FULLM, mx, o));

    float s = 0.f;
    for (int c = lane; c < C_; c += 32) s += expf(row[c] - mx);
    #pragma unroll
    for (int o = 16; o; o >>= 1) s += __shfl_xor_sync(FULLM, s, o);

    if (lane == 0) { g_smax[warp] = mx; g_ssum[warp] = s; }
}

// ---------------------------------------------------------------------------
// Kernel 2: cost matrix, transposed layout costT[b][m][n].
// ---------------------------------------------------------------------------
__global__ void cost_kernel(const float* __restrict__ logits,
                            const float* __restrict__ pboxes,
                            const int* __restrict__ tlabels,
                            const float* __restrict__ tboxes) {
    int m = blockIdx.x;
    int b = blockIdx.y;
    int idx = b * M_ + m;

    int cls = tlabels[idx];

    const float* tbp = tboxes + (size_t)idx * 4;
    float tcx = tbp[0], tcy = tbp[1], tw = tbp[2], th = tbp[3];
    float tx0 = tcx - 0.5f * tw, ty0 = tcy - 0.5f * th;
    float tx1 = tcx + 0.5f * tw, ty1 = tcy + 0.5f * th;
    float tarea = (tx1 - tx0) * (ty1 - ty0);

    float* out = g_costT + (size_t)idx * N_;

    for (int n = threadIdx.x; n < N_; n += blockDim.x) {
        size_t rn = (size_t)b * N_ + n;
        const float* pp = pboxes + rn * 4;
        float pcx = pp[0], pcy = pp[1], pw = pp[2], ph = pp[3];

        float l = logits[rn * C_ + cls];
        float prob = expf(l - g_smax[rn]) / g_ssum[rn];

        float l1 = fabsf(pcx - tcx) + fabsf(pcy - tcy)
                 + fabsf(pw - tw) + fabsf(ph - th);

        float px0 = pcx - 0.5f * pw, py0 = pcy - 0.5f * ph;
        float px1 = pcx + 0.5f * pw, py1 = pcy + 0.5f * ph;

        float iw = fmaxf(fminf(px1, tx1) - fmaxf(px0, tx0), 0.f);
        float ih = fmaxf(fminf(py1, ty1) - fmaxf(py0, ty0), 0.f);
        float inter = iw * ih;
        float area1 = (px1 - px0) * (py1 - py0);
        float uni = area1 + tarea - inter;
        float iou = inter / (uni + 1e-6f);
        float enc = (fmaxf(px1, tx1) - fminf(px0, tx0)) *
                    (fmaxf(py1, ty1) - fminf(py0, ty0)) + 1e-6f;
        float giou = iou - (enc - uni) / enc;

        out[n] = -prob + 5.f * l1 - 2.f * giou;
    }
}

// ---------------------------------------------------------------------------
// Kernel 3: Hungarian (successive shortest paths with potentials).
// Phase 1 (parallel): row reduction u[i]=min_j c[i][j] + greedy assignment
//   (argmin column, lowest row index wins collisions).
// Phase 2 (serial per free row): certified Dijkstra augmentation loop
//   (identical structure to R12). Produces THE optimal assignment; unique
//   optimum (continuous random costs) => identical to the reference.
// ---------------------------------------------------------------------------
__global__ void __launch_bounds__(TLSA, 1)
lsa_block_kernel() {
    int b = blockIdx.x;
    int tid = threadIdx.x;
    const float* cost = g_costT + (size_t)b * M_ * N_;

    __shared__ double u[M_ + 1];
    __shared__ int    p[N_ + 1];
    __shared__ int    way[N_ + 1];
    __shared__ float  rmin[M_];
    __shared__ int    rarg[M_];
    __shared__ int    owner[N_];
    __shared__ int    freelist[M_];
    __shared__ int    nfree_sh;
    __shared__ unsigned long long red_k[TLSA / 32];
    __shared__ int    red_j[TLSA / 32];
    __shared__ int    j0_sh, done_sh;
    __shared__ double delta_sh;
    __shared__ int    col4row[M_];

    const int cA = tid, cB = tid + 256, cC = tid + 512, cD = tid + 768;
    const bool ownD = (cD < N_);

    for (int j = tid; j <= N_; j += TLSA) p[j] = 0;
    for (int j = tid; j < N_; j += TLSA) owner[j] = 0x7FFFFFFF;
    __syncthreads();

    // ---- Phase 1: row minima (8 warps x 16 rows) ----
    {
        int w = tid >> 5, lane = tid & 31;
        for (int i = w; i < M_; i += TLSA / 32) {
            const float* crow = cost + (size_t)i * N_;
            float best = 1e30f; int bj = N_;
            for (int j = lane; j < N_; j += 32) {
                float c = crow[j];
                if (c < best || (c == best && j < bj)) { best = c; bj = j; }
            }
            #pragma unroll
            for (int o = 16; o; o >>= 1) {
                float ov = __shfl_down_sync(FULLM, best, o);
                int oj = __shfl_down_sync(FULLM, bj, o);
                if (ov < best || (ov == best && oj < bj)) { best = ov; bj = oj; }
            }
            if (lane == 0) { rmin[i] = best; rarg[i] = bj; }
        }
    }
    __syncthreads();

    if (tid < M_) {
        u[tid + 1] = (double)rmin[tid];
        atomicMin(&owner[rarg[tid]], tid);
    }
    if (tid == 0) u[0] = 0.0;
    __syncthreads();

    if (tid == 0) {
        int nf = 0;
        for (int i = 0; i < M_; ++i) {
            int j = rarg[i];
            if (owner[j] == i) p[j + 1] = i + 1;
            else               freelist[nf++] = i + 1;
        }
        nfree_sh = nf;
    }
    __syncthreads();
    int nfree = nfree_sh;

    // ---- Phase 2: augment remaining rows ----
    double vA = 0.0, vB = 0.0, vC = 0.0, vD = 0.0;
    double mA, mB, mC, mD;
    unsigned um;

    for (int k = 0; k < nfree; ++k) {
        int i = freelist[k];
        if (tid == 0) { p[0] = i; j0_sh = 0; done_sh = 0; }
        mA = INF_D; mB = INF_D; mC = INF_D; mD = INF_D;
        um = 0;
        bool first = true;

        while (true) {
            __syncthreads();                 // barrier A
            int j0 = j0_sh;

            if (!first) {
                double delta = delta_sh;
                if (um & 1u) { vA -= delta; u[p[cA + 1]] += delta; } else mA -= delta;
                if (um & 2u) { vB -= delta; u[p[cB + 1]] += delta; } else mB -= delta;
                if (um & 4u) { vC -= delta; u[p[cC + 1]] += delta; } else mC -= delta;
                if (ownD) {
                    if (um & 8u) { vD -= delta; u[p[cD + 1]] += delta; } else mD -= delta;
                }
            }
            if (done_sh) break;
            first = false;

            if (j0 >= 1) {
                int c = j0 - 1;
                if ((c & 255) == tid) um |= 1u << (c >> 8);
            }

            int i0 = p[j0];
            const float* crow = cost + (size_t)(i0 - 1) * N_;
            float fA = crow[cA];
            float fB = crow[cB];
            float fC = crow[cC];
            float fD = ownD ? crow[cD] : 0.f;
            double ui0 = u[i0];

            unsigned long long bk = 0xFFFFFFFFFFFFFFFFull;
            int bj = N_ + 2;
            if (!(um & 1u)) {
                double cur = (double)fA - ui0 - vA;
                if (cur < mA) { mA = cur; way[cA + 1] = j0; }
                unsigned long long kk = dmap(mA);
                if (kk < bk) { bk = kk; bj = cA + 1; }
            }
            if (!(um & 2u)) {
                double cur = (double)fB - ui0 - vB;
                if (cur < mB) { mB = cur; way[cB + 1] = j0; }
                unsigned long long kk = dmap(mB);
                if (kk < bk || (kk == bk && cB + 1 < bj)) { bk = kk; bj = cB + 1; }
            }
            if (!(um & 4u)) {
                double cur = (double)fC - ui0 - vC;
                if (cur < mC) { mC = cur; way[cC + 1] = j0; }
                unsigned long long kk = dmap(mC);
                if (kk < bk || (kk == bk && cC + 1 < bj)) { bk = kk; bj = cC + 1; }
            }
            if (ownD && !(um & 8u)) {
                double cur = (double)fD - ui0 - vD;
                if (cur < mD) { mD = cur; way[cD + 1] = j0; }
                unsigned long long kk = dmap(mD);
                if (kk < bk || (kk == bk && cD + 1 < bj)) { bk = kk; bj = cD + 1; }
            }

            #pragma unroll
            for (int o = 16; o; o >>= 1) {
                unsigned long long ok = __shfl_down_sync(FULLM, bk, o);
                int oj = __shfl_down_sync(FULLM, bj, o);
                if (ok < bk || (ok == bk && oj < bj)) { bk = ok; bj = oj; }
            }
            if ((tid & 31) == 0) { red_k[tid >> 5] = bk; red_j[tid >> 5] = bj; }
            __syncthreads();                 // barrier B

            if (tid < 32) {
                unsigned long long fk = (tid < TLSA / 32) ? red_k[tid]
                                                          : 0xFFFFFFFFFFFFFFFFull;
                int fj = (tid < TLSA / 32) ? red_j[tid] : N_ + 2;
                #pragma unroll
                for (int o = 4; o; o >>= 1) {
                    unsigned long long ok = __shfl_down_sync(FULLM, fk, o);
                    int oj = __shfl_down_sync(FULLM, fj, o);
                    if (ok < fk || (ok == fk && oj < fj)) { fk = ok; fj = oj; }
                }
                if (tid == 0) {
                    double delta = dunmap(fk);
                    delta_sh = delta;
                    u[p[0]] += delta;
                    j0_sh = fj;
                    done_sh = (p[fj] == 0);
                }
            }
        }

        if (tid == 0) {
            int jj = j0_sh;
            while (jj) { int jn = way[jj]; p[jj] = p[jn]; jj = jn; }
        }
    }
    __syncthreads();

    for (int j = 1 + tid; j <= N_; j += TLSA)
        if (p[j] > 0) col4row[p[j] - 1] = j - 1;
    __syncthreads();

    if (tid < M_) {
        int vme = col4row[tid];
        int r = 0;
        #pragma unroll 8
        for (int k = 0; k < M_; ++k) r += (col4row[k] < vme);
        g_rows[b * M_ + r] = vme;
        g_cols[b * M_ + r] = tid;
    }
}

// ---------------------------------------------------------------------------
// Kernel 4: emit output as FLOAT32 (harness compares output.bin as float32).
// ---------------------------------------------------------------------------
__global__ void emit_kernel(float* __restrict__ d_out) {
    int i = blockIdx.x * blockDim.x + threadIdx.x;
    if (i >= 2 * B_ * M_) return;
    int val = (i < B_ * M_) ? g_rows[i] : g_cols[i - B_ * M_];
    d_out[i] = (float)val;
}

// ---------------------------------------------------------------------------
extern "C" void kernel_launch(void* const* d_in, const int* in_sizes, int n_in,
                              void* d_out, int out_size) {
    const float* logits  = (const float*)d_in[0];
    const float* pboxes  = (const float*)d_in[1];
    const int*   tlabels = (const int*)d_in[2];
    const float* tboxes  = (const float*)d_in[3];

    softmax_stats_kernel<<<(B_ * N_ * 32 + 255) / 256, 256>>>(logits);
    {
        dim3 grid(M_, B_);
        cost_kernel<<<grid, 256>>>(logits, pboxes, tlabels, tboxes);
    }
    lsa_block_kernel<<<B_, TLSA>>>();
    emit_kernel<<<(2 * B_ * M_ + 255) / 256, 256>>>((float*)d_out);
}